// round 3
// baseline (speedup 1.0000x reference)
#include <cuda_runtime.h>
#include <cuda_bf16.h>
#include <cstdint>

#define B_  2
#define N_  2048
#define D_  1024
#define H_  8
#define DK_ 128
#define DV_ 1024

using bf16 = __nv_bfloat16;

// Static scratch (no cudaMalloc allowed).
__device__ bf16 g_Xb [(size_t)B_ * N_ * D_];
__device__ bf16 g_Wqb[(size_t)H_ * DK_ * D_];
__device__ bf16 g_Wkb[(size_t)H_ * DK_ * D_];
__device__ bf16 g_Wvb[(size_t)H_ * DV_ * D_];
__device__ bf16 g_Q  [(size_t)B_ * H_ * N_ * DK_];
__device__ bf16 g_K  [(size_t)B_ * H_ * N_ * DK_];
__device__ bf16 g_V  [(size_t)B_ * H_ * N_ * DV_];

// ---------------------------------------------------------------------------
// helpers
// ---------------------------------------------------------------------------
__device__ __forceinline__ uint32_t smem_u32(const void* p) {
  return (uint32_t)__cvta_generic_to_shared(p);
}
__device__ __forceinline__ void ldmx4(uint32_t& r0, uint32_t& r1, uint32_t& r2,
                                      uint32_t& r3, uint32_t addr) {
  asm volatile("ldmatrix.sync.aligned.m8n8.x4.shared.b16 {%0,%1,%2,%3},[%4];"
               : "=r"(r0), "=r"(r1), "=r"(r2), "=r"(r3) : "r"(addr));
}
__device__ __forceinline__ void ldmx4t(uint32_t& r0, uint32_t& r1, uint32_t& r2,
                                       uint32_t& r3, uint32_t addr) {
  asm volatile("ldmatrix.sync.aligned.m8n8.x4.trans.shared.b16 {%0,%1,%2,%3},[%4];"
               : "=r"(r0), "=r"(r1), "=r"(r2), "=r"(r3) : "r"(addr));
}
__device__ __forceinline__ void mma16816(float* c, uint32_t a0, uint32_t a1,
                                         uint32_t a2, uint32_t a3, uint32_t b0,
                                         uint32_t b1) {
  asm volatile(
      "mma.sync.aligned.m16n8k16.row.col.f32.bf16.bf16.f32 "
      "{%0,%1,%2,%3},{%4,%5,%6,%7},{%8,%9},{%0,%1,%2,%3};"
      : "+f"(c[0]), "+f"(c[1]), "+f"(c[2]), "+f"(c[3])
      : "r"(a0), "r"(a1), "r"(a2), "r"(a3), "r"(b0), "r"(b1));
}
__device__ __forceinline__ uint32_t packbf(float lo, float hi) {
  uint32_t r;
  asm("cvt.rn.bf16x2.f32 %0, %1, %2;" : "=r"(r) : "f"(hi), "f"(lo));
  return r;
}
__device__ __forceinline__ void cpa16(uint32_t dst, const void* src) {
  asm volatile("cp.async.cg.shared.global [%0], [%1], 16;" :: "r"(dst), "l"(src));
}
__device__ __forceinline__ void cp_commit() {
  asm volatile("cp.async.commit_group;");
}
template <int N>
__device__ __forceinline__ void cp_wait() {
  asm volatile("cp.async.wait_group %0;" :: "n"(N));
}

// ---------------------------------------------------------------------------
// fp32 -> bf16 cast
// ---------------------------------------------------------------------------
__global__ void cast_kernel(const float* __restrict__ src, bf16* __restrict__ dst,
                            int n4) {
  int i = blockIdx.x * blockDim.x + threadIdx.x;
  if (i < n4) {
    float4 v = ((const float4*)src)[i];
    ((__nv_bfloat162*)dst)[2 * i]     = __floats2bfloat162_rn(v.x, v.y);
    ((__nv_bfloat162*)dst)[2 * i + 1] = __floats2bfloat162_rn(v.z, v.w);
  }
}

// ---------------------------------------------------------------------------
// Projection GEMM (bf16 HMMA, cp.async double-buffered):
//   out[bh][n][e] = sum_d X[b,n,d] * W[h,e,d]
// 128x128 tile, 8 warps, k-step 64, 2-stage pipeline. smem stride 72 (144B).
// ---------------------------------------------------------------------------
template <int E>
__global__ __launch_bounds__(256) void proj_mma(const bf16* __restrict__ Xb,
                                                const bf16* __restrict__ Wb,
                                                bf16* __restrict__ out) {
  extern __shared__ bf16 psm[];
  bf16* Xs = psm;                 // [2][128*72]
  bf16* Ws = psm + 2 * 128 * 72;  // [2][128*72]

  const int bh = blockIdx.z, b = bh >> 3, h = bh & 7;
  const int n0 = blockIdx.y * 128, e0 = blockIdx.x * 128;
  const bf16* Xg = Xb + ((size_t)(b * N_ + n0)) * D_;
  const bf16* Wg = Wb + ((size_t)h * E + e0) * (size_t)D_;

  const int tid = threadIdx.x, warp = tid >> 5, lane = tid & 31;
  const int gid = lane >> 2, tig = lane & 3;
  const int m0 = warp * 16;

  auto load_stage = [&](int k0, int buf) {
    bf16* xd = Xs + buf * 128 * 72;
    bf16* wd = Ws + buf * 128 * 72;
#pragma unroll
    for (int r = 0; r < 4; ++r) {
      int f = tid + 256 * r;
      int row = f >> 3, c8 = (f & 7) * 8;
      cpa16(smem_u32(xd + row * 72 + c8), Xg + (size_t)row * D_ + k0 + c8);
      cpa16(smem_u32(wd + row * 72 + c8), Wg + (size_t)row * D_ + k0 + c8);
    }
  };

  float acc[16][4] = {};

  load_stage(0, 0);
  cp_commit();

  const int NS = D_ / 64;  // 16 stages
  for (int s = 0; s < NS; ++s) {
    if (s + 1 < NS) {
      load_stage((s + 1) * 64, (s + 1) & 1);
      cp_commit();
      cp_wait<1>();
    } else {
      cp_wait<0>();
    }
    __syncthreads();

    const uint32_t xs = smem_u32(Xs + (s & 1) * 128 * 72);
    const uint32_t ws = smem_u32(Ws + (s & 1) * 128 * 72);
#pragma unroll
    for (int kk = 0; kk < 64; kk += 16) {
      uint32_t a0, a1, a2, a3;
      {
        int m = lane >> 3;
        int row = m0 + (lane & 7) + (m & 1) * 8;
        int col = kk + (m >> 1) * 8;
        ldmx4(a0, a1, a2, a3, xs + (uint32_t)(row * 72 + col) * 2);
      }
#pragma unroll
      for (int j = 0; j < 16; j += 2) {
        uint32_t b0, b1, b2, b3;
        int m = lane >> 3;
        int row = j * 8 + (lane & 7) + (m >> 1) * 8;
        int col = kk + (m & 1) * 8;
        ldmx4(b0, b1, b2, b3, ws + (uint32_t)(row * 72 + col) * 2);
        mma16816(acc[j],     a0, a1, a2, a3, b0, b1);
        mma16816(acc[j + 1], a0, a1, a2, a3, b2, b3);
      }
    }
    __syncthreads();
  }

  bf16* og = out + ((size_t)bh * N_ + n0) * E + e0;
#pragma unroll
  for (int j = 0; j < 16; ++j) {
    int col = j * 8 + tig * 2;
    *(uint32_t*)(og + (size_t)(m0 + gid) * E + col)     = packbf(acc[j][0], acc[j][1]);
    *(uint32_t*)(og + (size_t)(m0 + gid + 8) * E + col) = packbf(acc[j][2], acc[j][3]);
  }
}

// ---------------------------------------------------------------------------
// Fused causal relu-attention + residual, bf16 HMMA, cp.async 2-stage.
// Block: 256 thr / 8 warps; q-tile 128, v-chunk 128; warp owns 16 q rows.
// ---------------------------------------------------------------------------
__global__ __launch_bounds__(256) void attn_mma(const float* __restrict__ X,
                                                float* __restrict__ out) {
  extern __shared__ bf16 sm[];
  bf16* Qs = sm;                  // [128][136]
  bf16* Ks = Qs + 128 * 136;      // [2][64][136]
  bf16* Vs = Ks + 2 * 64 * 136;   // [2][64][136]

  const int b  = blockIdx.z;
  const int qi = blockIdx.y;
  const int q0 = qi * 128;
  const int v0 = blockIdx.x * 128;
  const int tid = threadIdx.x, warp = tid >> 5, lane = tid & 31;
  const int gid = lane >> 2, tig = lane & 3;
  const float invN = 1.0f / (float)N_;

  const int r0 = q0 + warp * 16 + gid;
  const int r1 = r0 + 8;
  const int nkt = 2 * qi + 2;  // causal 64-key tiles

  float oacc[16][4] = {};

  for (int h = 0; h < H_; ++h) {
    const size_t bh = (size_t)(b * H_ + h);
    const bf16* Qg = g_Q + (bh * N_ + q0) * DK_;
    const bf16* Kb = g_K + bh * N_ * DK_;
    const bf16* Vb = g_V + bh * N_ * DV_ + v0;

    auto kv_load = [&](int kt, int buf) {
      const bf16* Kg = Kb + (size_t)kt * 64 * DK_;
      const bf16* Vg = Vb + (size_t)kt * 64 * DV_;
      bf16* kd = Ks + buf * 64 * 136;
      bf16* vd = Vs + buf * 64 * 136;
#pragma unroll
      for (int r = 0; r < 4; ++r) {
        int f = tid + 256 * r;
        int row = f >> 4, c8 = (f & 15) * 8;
        cpa16(smem_u32(kd + row * 136 + c8), Kg + (size_t)row * DK_ + c8);
        cpa16(smem_u32(vd + row * 136 + c8), Vg + (size_t)row * DV_ + c8);
      }
    };

    // group 0: Q tile + first K/V tile
#pragma unroll
    for (int r = 0; r < 8; ++r) {
      int f = tid + 256 * r;
      int row = f >> 4, c8 = (f & 15) * 8;
      cpa16(smem_u32(Qs + row * 136 + c8), Qg + (size_t)row * DK_ + c8);
    }
    kv_load(0, 0);
    cp_commit();

    for (int kt = 0; kt < nkt; ++kt) {
      if (kt + 1 < nkt) {
        kv_load(kt + 1, (kt + 1) & 1);
        cp_commit();
        cp_wait<1>();
      } else {
        cp_wait<0>();
      }
      __syncthreads();

      const int buf = kt & 1;
      const int k0 = kt * 64;
      const uint32_t qs = smem_u32(Qs);
      const uint32_t ks = smem_u32(Ks + buf * 64 * 136);
      const uint32_t vs = smem_u32(Vs + buf * 64 * 136);

      // ---- S = Q K^T  (16 q-rows x 64 keys per warp) ----
      float sf[8][4] = {};
#pragma unroll
      for (int kk = 0; kk < DK_; kk += 16) {
        uint32_t a0, a1, a2, a3;
        {
          int m = lane >> 3;
          int row = warp * 16 + (lane & 7) + (m & 1) * 8;
          int col = kk + (m >> 1) * 8;
          ldmx4(a0, a1, a2, a3, qs + (uint32_t)(row * 136 + col) * 2);
        }
#pragma unroll
        for (int j = 0; j < 8; j += 2) {
          uint32_t b0, b1, b2, b3;
          int m = lane >> 3;
          int row = j * 8 + (lane & 7) + (m >> 1) * 8;
          int col = kk + (m & 1) * 8;
          ldmx4(b0, b1, b2, b3, ks + (uint32_t)(row * 136 + col) * 2);
          mma16816(sf[j],     a0, a1, a2, a3, b0, b1);
          mma16816(sf[j + 1], a0, a1, a2, a3, b2, b3);
        }
      }

      // ---- mask + relu + /N, repack C-frags as A-frags ----
      uint32_t sA[4][4];
#pragma unroll
      for (int g = 0; g < 8; ++g) {
        int key = k0 + g * 8 + tig * 2;
        float v0f = (key     <= r0) ? fmaxf(sf[g][0], 0.f) * invN : 0.f;
        float v1f = (key + 1 <= r0) ? fmaxf(sf[g][1], 0.f) * invN : 0.f;
        float v2f = (key     <= r1) ? fmaxf(sf[g][2], 0.f) * invN : 0.f;
        float v3f = (key + 1 <= r1) ? fmaxf(sf[g][3], 0.f) * invN : 0.f;
        int ki = g >> 1;
        if (!(g & 1)) {
          sA[ki][0] = packbf(v0f, v1f);
          sA[ki][1] = packbf(v2f, v3f);
        } else {
          sA[ki][2] = packbf(v0f, v1f);
          sA[ki][3] = packbf(v2f, v3f);
        }
      }

      // ---- O += S @ V ----
#pragma unroll
      for (int ki = 0; ki < 4; ++ki) {
#pragma unroll
        for (int j = 0; j < 16; j += 2) {
          uint32_t b0, b1, b2, b3;
          int m = lane >> 3;
          int row = ki * 16 + (m & 1) * 8 + (lane & 7);
          int col = j * 8 + (m >> 1) * 8;
          ldmx4t(b0, b1, b2, b3, vs + (uint32_t)(row * 136 + col) * 2);
          mma16816(oacc[j],     sA[ki][0], sA[ki][1], sA[ki][2], sA[ki][3], b0, b1);
          mma16816(oacc[j + 1], sA[ki][0], sA[ki][1], sA[ki][2], sA[ki][3], b2, b3);
        }
      }
      __syncthreads();
    }
  }

  // ---- epilogue: out = x + O (fp32) ----
  const float* xg = X + ((size_t)b * N_ + q0 + warp * 16) * DV_ + v0;
  float* og = out + ((size_t)b * N_ + q0 + warp * 16) * DV_ + v0;
#pragma unroll
  for (int j = 0; j < 16; ++j) {
    int col = j * 8 + tig * 2;
    float2 a = *(const float2*)(xg + (size_t)gid * DV_ + col);
    float2 c = *(const float2*)(xg + (size_t)(gid + 8) * DV_ + col);
    *(float2*)(og + (size_t)gid * DV_ + col) =
        make_float2(a.x + oacc[j][0], a.y + oacc[j][1]);
    *(float2*)(og + (size_t)(gid + 8) * DV_ + col) =
        make_float2(c.x + oacc[j][2], c.y + oacc[j][3]);
  }
}

// ---------------------------------------------------------------------------
extern "C" void kernel_launch(void* const* d_in, const int* in_sizes, int n_in,
                              void* d_out, int out_size) {
  const float* x  = (const float*)d_in[0];
  const float* Wq = (const float*)d_in[1];
  const float* Wk = (const float*)d_in[2];
  const float* Wv = (const float*)d_in[3];
  float* out = (float*)d_out;

  bf16 *Xb, *Wqb, *Wkb, *Wvb, *Qb, *Kb, *Vb;
  cudaGetSymbolAddress((void**)&Xb,  g_Xb);
  cudaGetSymbolAddress((void**)&Wqb, g_Wqb);
  cudaGetSymbolAddress((void**)&Wkb, g_Wkb);
  cudaGetSymbolAddress((void**)&Wvb, g_Wvb);
  cudaGetSymbolAddress((void**)&Qb,  g_Q);
  cudaGetSymbolAddress((void**)&Kb,  g_K);
  cudaGetSymbolAddress((void**)&Vb,  g_V);

  auto cast = [&](const float* s, bf16* d, int n) {
    int n4 = n / 4;
    cast_kernel<<<(n4 + 255) / 256, 256>>>(s, d, n4);
  };
  cast(x,  Xb,  B_ * N_ * D_);
  cast(Wq, Wqb, H_ * DK_ * D_);
  cast(Wk, Wkb, H_ * DK_ * D_);
  cast(Wv, Wvb, H_ * DV_ * D_);

  const int proj_smem = 2 * 2 * 128 * 72 * (int)sizeof(bf16);  // 73728
  cudaFuncSetAttribute(proj_mma<DK_>,
                       cudaFuncAttributeMaxDynamicSharedMemorySize, proj_smem);
  cudaFuncSetAttribute(proj_mma<DV_>,
                       cudaFuncAttributeMaxDynamicSharedMemorySize, proj_smem);
  proj_mma<DK_><<<dim3(1, 16, 16), 256, proj_smem>>>(Xb, Wqb, Qb);
  proj_mma<DK_><<<dim3(1, 16, 16), 256, proj_smem>>>(Xb, Wkb, Kb);
  proj_mma<DV_><<<dim3(8, 16, 16), 256, proj_smem>>>(Xb, Wvb, Vb);

  const int attn_smem = (128 + 4 * 64) * 136 * (int)sizeof(bf16);  // 104448
  cudaFuncSetAttribute(attn_mma,
                       cudaFuncAttributeMaxDynamicSharedMemorySize, attn_smem);
  attn_mma<<<dim3(8, 16, 2), 256, attn_smem>>>(x, out);
}

// round 5
// speedup vs baseline: 1.0763x; 1.0763x over previous
#include <cuda_runtime.h>
#include <cuda_bf16.h>
#include <cstdint>

#define B_  2
#define N_  2048
#define D_  1024
#define H_  8
#define DK_ 128
#define DV_ 1024

using bf16 = __nv_bfloat16;

// Static scratch (no cudaMalloc allowed).
__device__ bf16 g_Xb [(size_t)B_ * N_ * D_];
__device__ bf16 g_Wqb[(size_t)H_ * DK_ * D_];
__device__ bf16 g_Wkb[(size_t)H_ * DK_ * D_];
__device__ bf16 g_Wvb[(size_t)H_ * DV_ * D_];
__device__ bf16 g_Q  [(size_t)B_ * H_ * N_ * DK_];
__device__ bf16 g_K  [(size_t)B_ * H_ * N_ * DK_];
__device__ bf16 g_V  [(size_t)B_ * H_ * N_ * DV_];
__device__ bf16 g_S  [(size_t)B_ * H_ * N_ * N_];   // 134 MB masked scores

// ---------------------------------------------------------------------------
// helpers
// ---------------------------------------------------------------------------
__device__ __forceinline__ uint32_t smem_u32(const void* p) {
  return (uint32_t)__cvta_generic_to_shared(p);
}
__device__ __forceinline__ void ldmx4(uint32_t& r0, uint32_t& r1, uint32_t& r2,
                                      uint32_t& r3, uint32_t addr) {
  asm volatile("ldmatrix.sync.aligned.m8n8.x4.shared.b16 {%0,%1,%2,%3},[%4];"
               : "=r"(r0), "=r"(r1), "=r"(r2), "=r"(r3) : "r"(addr));
}
__device__ __forceinline__ void ldmx4t(uint32_t& r0, uint32_t& r1, uint32_t& r2,
                                       uint32_t& r3, uint32_t addr) {
  asm volatile("ldmatrix.sync.aligned.m8n8.x4.trans.shared.b16 {%0,%1,%2,%3},[%4];"
               : "=r"(r0), "=r"(r1), "=r"(r2), "=r"(r3) : "r"(addr));
}
__device__ __forceinline__ void mma16816(float* c, uint32_t a0, uint32_t a1,
                                         uint32_t a2, uint32_t a3, uint32_t b0,
                                         uint32_t b1) {
  asm volatile(
      "mma.sync.aligned.m16n8k16.row.col.f32.bf16.bf16.f32 "
      "{%0,%1,%2,%3},{%4,%5,%6,%7},{%8,%9},{%0,%1,%2,%3};"
      : "+f"(c[0]), "+f"(c[1]), "+f"(c[2]), "+f"(c[3])
      : "r"(a0), "r"(a1), "r"(a2), "r"(a3), "r"(b0), "r"(b1));
}
__device__ __forceinline__ uint32_t packbf(float lo, float hi) {
  uint32_t r;
  asm("cvt.rn.bf16x2.f32 %0, %1, %2;" : "=r"(r) : "f"(hi), "f"(lo));
  return r;
}

// ---------------------------------------------------------------------------
// fp32 -> bf16 cast
// ---------------------------------------------------------------------------
__global__ void cast_kernel(const float* __restrict__ src, bf16* __restrict__ dst,
                            int n4) {
  int i = blockIdx.x * blockDim.x + threadIdx.x;
  if (i < n4) {
    float4 v = ((const float4*)src)[i];
    ((__nv_bfloat162*)dst)[2 * i]     = __floats2bfloat162_rn(v.x, v.y);
    ((__nv_bfloat162*)dst)[2 * i + 1] = __floats2bfloat162_rn(v.z, v.w);
  }
}

// ---------------------------------------------------------------------------
// Projection GEMM (bf16 HMMA): out[bh][n][e] = sum_d X[b,n,d] * W[h,e,d]
// 128x128 tile, 8 warps, k-step 64. (R2 measured-best version.)
// ---------------------------------------------------------------------------
template <int E>
__global__ __launch_bounds__(256) void proj_mma(const bf16* __restrict__ Xb,
                                                const bf16* __restrict__ Wb,
                                                bf16* __restrict__ out) {
  __shared__ bf16 Xs[128 * 72];
  __shared__ bf16 Ws[128 * 72];

  const int bh = blockIdx.z, b = bh >> 3, h = bh & 7;
  const int n0 = blockIdx.y * 128, e0 = blockIdx.x * 128;
  const bf16* Xg = Xb + ((size_t)(b * N_ + n0)) * D_;
  const bf16* Wg = Wb + ((size_t)h * E + e0) * (size_t)D_;

  const int tid = threadIdx.x, warp = tid >> 5, lane = tid & 31;
  const int gid = lane >> 2, tig = lane & 3;
  const int m0 = warp * 16;
  const uint32_t xs = smem_u32(Xs), ws = smem_u32(Ws);

  float acc[16][4] = {};

  for (int k0 = 0; k0 < D_; k0 += 64) {
#pragma unroll
    for (int r = 0; r < 4; ++r) {
      int f = tid + 256 * r;
      int row = f >> 3, c8 = (f & 7) * 8;
      *(uint4*)&Xs[row * 72 + c8] = *(const uint4*)(Xg + (size_t)row * D_ + k0 + c8);
      *(uint4*)&Ws[row * 72 + c8] = *(const uint4*)(Wg + (size_t)row * D_ + k0 + c8);
    }
    __syncthreads();

#pragma unroll
    for (int kk = 0; kk < 64; kk += 16) {
      uint32_t a0, a1, a2, a3;
      {
        int m = lane >> 3;
        int row = m0 + (lane & 7) + (m & 1) * 8;
        int col = kk + (m >> 1) * 8;
        ldmx4(a0, a1, a2, a3, xs + (uint32_t)(row * 72 + col) * 2);
      }
#pragma unroll
      for (int j = 0; j < 16; j += 2) {
        uint32_t b0, b1, b2, b3;
        int m = lane >> 3;
        int row = j * 8 + (lane & 7) + (m >> 1) * 8;
        int col = kk + (m & 1) * 8;
        ldmx4(b0, b1, b2, b3, ws + (uint32_t)(row * 72 + col) * 2);
        mma16816(acc[j],     a0, a1, a2, a3, b0, b1);
        mma16816(acc[j + 1], a0, a1, a2, a3, b2, b3);
      }
    }
    __syncthreads();
  }

  bf16* og = out + ((size_t)bh * N_ + n0) * E + e0;
#pragma unroll
  for (int j = 0; j < 16; ++j) {
    int col = j * 8 + tig * 2;
    *(uint32_t*)(og + (size_t)(m0 + gid) * E + col)     = packbf(acc[j][0], acc[j][1]);
    *(uint32_t*)(og + (size_t)(m0 + gid + 8) * E + col) = packbf(acc[j][2], acc[j][3]);
  }
}

// ---------------------------------------------------------------------------
// Score kernel: S[bh][n][m] = (m<=n) ? relu(Q.K^T)/N : 0, bf16.
// Only lower-triangular 128x128 tiles launched do work; others exit.
// 256 threads / 8 warps; warp owns 16 q-rows x 128 keys.
// ---------------------------------------------------------------------------
__global__ __launch_bounds__(256) void score_mma(void) {
  const int ki = blockIdx.x, qi = blockIdx.y;
  if (ki > qi) return;
  const int bh = blockIdx.z;

  extern __shared__ bf16 ssm[];
  bf16* Qs = ssm;               // [128][136]
  bf16* Ks = Qs + 128 * 136;    // [128][136]

  const int q0 = qi * 128, k0 = ki * 128;
  const int tid = threadIdx.x, warp = tid >> 5, lane = tid & 31;
  const int gid = lane >> 2, tig = lane & 3;
  const uint32_t qs = smem_u32(Qs), ks = smem_u32(Ks);
  const float invN = 1.0f / (float)N_;

  const bf16* Qg = g_Q + ((size_t)bh * N_ + q0) * DK_;
  const bf16* Kg = g_K + ((size_t)bh * N_ + k0) * DK_;

#pragma unroll
  for (int r = 0; r < 8; ++r) {
    int f = tid + 256 * r;
    int row = f >> 4, c8 = (f & 15) * 8;
    *(uint4*)&Qs[row * 136 + c8] = *(const uint4*)(Qg + (size_t)row * DK_ + c8);
    *(uint4*)&Ks[row * 136 + c8] = *(const uint4*)(Kg + (size_t)row * DK_ + c8);
  }
  __syncthreads();

  float sf[16][4] = {};
#pragma unroll
  for (int kk = 0; kk < DK_; kk += 16) {
    uint32_t a0, a1, a2, a3;
    {
      int m = lane >> 3;
      int row = warp * 16 + (lane & 7) + (m & 1) * 8;
      int col = kk + (m >> 1) * 8;
      ldmx4(a0, a1, a2, a3, qs + (uint32_t)(row * 136 + col) * 2);
    }
#pragma unroll
    for (int j = 0; j < 16; j += 2) {
      uint32_t b0, b1, b2, b3;
      int m = lane >> 3;
      int row = j * 8 + (lane & 7) + (m >> 1) * 8;
      int col = kk + (m & 1) * 8;
      ldmx4(b0, b1, b2, b3, ks + (uint32_t)(row * 136 + col) * 2);
      mma16816(sf[j],     a0, a1, a2, a3, b0, b1);
      mma16816(sf[j + 1], a0, a1, a2, a3, b2, b3);
    }
  }

  // mask + relu + /N, store bf16 to g_S
  const int r0 = q0 + warp * 16 + gid;
  const int r1 = r0 + 8;
  bf16* Sg = g_S + (size_t)bh * N_ * N_;
#pragma unroll
  for (int g = 0; g < 16; ++g) {
    int c = k0 + g * 8 + tig * 2;
    float v0f = (c     <= r0) ? fmaxf(sf[g][0], 0.f) * invN : 0.f;
    float v1f = (c + 1 <= r0) ? fmaxf(sf[g][1], 0.f) * invN : 0.f;
    float v2f = (c     <= r1) ? fmaxf(sf[g][2], 0.f) * invN : 0.f;
    float v3f = (c + 1 <= r1) ? fmaxf(sf[g][3], 0.f) * invN : 0.f;
    *(uint32_t*)(Sg + (size_t)r0 * N_ + c) = packbf(v0f, v1f);
    *(uint32_t*)(Sg + (size_t)r1 * N_ + c) = packbf(v2f, v3f);
  }
}

// ---------------------------------------------------------------------------
// PV GEMM + residual: out[b][n][v] = x + sum_h sum_m S[bh][n][m] * V[bh][m][v]
// Block: (v-chunk 128, q-tile 128, b). 256 threads / 8 warps.
// K-loop: h (8) x key tiles of 64 (only m < q0+128).
// ---------------------------------------------------------------------------
__global__ __launch_bounds__(256) void pv_mma(const float* __restrict__ X,
                                              float* __restrict__ out) {
  extern __shared__ bf16 psm[];
  bf16* Ss = psm;               // [128][72]
  bf16* Vs = Ss + 128 * 72;     // [64][136]

  const int b  = blockIdx.z;
  const int qi = blockIdx.y;
  const int q0 = qi * 128;
  const int v0 = blockIdx.x * 128;
  const int tid = threadIdx.x, warp = tid >> 5, lane = tid & 31;
  const int gid = lane >> 2, tig = lane & 3;
  const uint32_t ss = smem_u32(Ss), vs = smem_u32(Vs);
  const int nkt = 2 * qi + 2;  // 64-wide key tiles, m < q0+128

  float oacc[16][4] = {};

  for (int h = 0; h < H_; ++h) {
    const size_t bh = (size_t)(b * H_ + h);
    const bf16* Sg = g_S + (bh * N_ + q0) * (size_t)N_;
    const bf16* Vg = g_V + bh * (size_t)N_ * DV_ + v0;

    for (int kt = 0; kt < nkt; ++kt) {
      const int k0 = kt * 64;
      __syncthreads();
      // S tile [128 x 64], V tile [64 x 128] : 4 x 16B per thread each
#pragma unroll
      for (int r = 0; r < 4; ++r) {
        int f = tid + 256 * r;
        int srow = f >> 3, sc8 = (f & 7) * 8;
        *(uint4*)&Ss[srow * 72 + sc8] =
            *(const uint4*)(Sg + (size_t)srow * N_ + k0 + sc8);
        int vrow = f >> 4, vc8 = (f & 15) * 8;
        *(uint4*)&Vs[vrow * 136 + vc8] =
            *(const uint4*)(Vg + (size_t)(k0 + vrow) * DV_ + vc8);
      }
      __syncthreads();

#pragma unroll
      for (int kk = 0; kk < 64; kk += 16) {
        uint32_t a0, a1, a2, a3;
        {
          int m = lane >> 3;
          int row = warp * 16 + (lane & 7) + (m & 1) * 8;
          int col = kk + (m >> 1) * 8;
          ldmx4(a0, a1, a2, a3, ss + (uint32_t)(row * 72 + col) * 2);
        }
#pragma unroll
        for (int j = 0; j < 16; j += 2) {
          uint32_t b0, b1, b2, b3;
          int m = lane >> 3;
          int row = kk + (m & 1) * 8 + (lane & 7);
          int col = j * 8 + (m >> 1) * 8;
          ldmx4t(b0, b1, b2, b3, vs + (uint32_t)(row * 136 + col) * 2);
          mma16816(oacc[j],     a0, a1, a2, a3, b0, b1);
          mma16816(oacc[j + 1], a0, a1, a2, a3, b2, b3);
        }
      }
    }
  }

  // epilogue: out = x + O
  const float* xg = X + ((size_t)b * N_ + q0 + warp * 16) * DV_ + v0;
  float* og = out + ((size_t)b * N_ + q0 + warp * 16) * DV_ + v0;
#pragma unroll
  for (int j = 0; j < 16; ++j) {
    int col = j * 8 + tig * 2;
    float2 a = *(const float2*)(xg + (size_t)gid * DV_ + col);
    float2 c = *(const float2*)(xg + (size_t)(gid + 8) * DV_ + col);
    *(float2*)(og + (size_t)gid * DV_ + col) =
        make_float2(a.x + oacc[j][0], a.y + oacc[j][1]);
    *(float2*)(og + (size_t)(gid + 8) * DV_ + col) =
        make_float2(c.x + oacc[j][2], c.y + oacc[j][3]);
  }
}

// ---------------------------------------------------------------------------
extern "C" void kernel_launch(void* const* d_in, const int* in_sizes, int n_in,
                              void* d_out, int out_size) {
  const float* x  = (const float*)d_in[0];
  const float* Wq = (const float*)d_in[1];
  const float* Wk = (const float*)d_in[2];
  const float* Wv = (const float*)d_in[3];
  float* out = (float*)d_out;

  bf16 *Xb, *Wqb, *Wkb, *Wvb, *Qb, *Kb, *Vb;
  cudaGetSymbolAddress((void**)&Xb,  g_Xb);
  cudaGetSymbolAddress((void**)&Wqb, g_Wqb);
  cudaGetSymbolAddress((void**)&Wkb, g_Wkb);
  cudaGetSymbolAddress((void**)&Wvb, g_Wvb);
  cudaGetSymbolAddress((void**)&Qb,  g_Q);
  cudaGetSymbolAddress((void**)&Kb,  g_K);
  cudaGetSymbolAddress((void**)&Vb,  g_V);

  auto cast = [&](const float* s, bf16* d, int n) {
    int n4 = n / 4;
    cast_kernel<<<(n4 + 255) / 256, 256>>>(s, d, n4);
  };
  cast(x,  Xb,  B_ * N_ * D_);
  cast(Wq, Wqb, H_ * DK_ * D_);
  cast(Wk, Wkb, H_ * DK_ * D_);
  cast(Wv, Wvb, H_ * DV_ * D_);

  proj_mma<DK_><<<dim3(1, 16, 16), 256>>>(Xb, Wqb, Qb);
  proj_mma<DK_><<<dim3(1, 16, 16), 256>>>(Xb, Wkb, Kb);
  proj_mma<DV_><<<dim3(8, 16, 16), 256>>>(Xb, Wvb, Vb);

  const int score_smem = 2 * 128 * 136 * (int)sizeof(bf16);  // 69632
  cudaFuncSetAttribute(score_mma, cudaFuncAttributeMaxDynamicSharedMemorySize,
                       score_smem);
  score_mma<<<dim3(16, 16, 16), 256, score_smem>>>();

  const int pv_smem = (128 * 72 + 64 * 136) * (int)sizeof(bf16);  // 35840
  cudaFuncSetAttribute(pv_mma, cudaFuncAttributeMaxDynamicSharedMemorySize,
                       pv_smem);
  pv_mma<<<dim3(8, 16, 2), 256, pv_smem>>>(x, out);
}

// round 6
// speedup vs baseline: 1.1555x; 1.0736x over previous
#include <cuda_runtime.h>
#include <cuda_bf16.h>
#include <cstdint>

#define B_  2
#define N_  2048
#define D_  1024
#define H_  8
#define DK_ 128
#define DV_ 1024

using bf16 = __nv_bfloat16;

// Static scratch (no cudaMalloc allowed).
__device__ bf16 g_Xb [(size_t)B_ * N_ * D_];
__device__ bf16 g_Wqb[(size_t)H_ * DK_ * D_];
__device__ bf16 g_Wkb[(size_t)H_ * DK_ * D_];
__device__ bf16 g_Wvb[(size_t)H_ * DV_ * D_];
__device__ bf16 g_Q  [(size_t)B_ * H_ * N_ * DK_];
__device__ bf16 g_K  [(size_t)B_ * H_ * N_ * DK_];
__device__ bf16 g_V  [(size_t)B_ * H_ * N_ * DV_];
__device__ bf16 g_S  [(size_t)B_ * H_ * N_ * N_];   // 134 MB masked scores

// ---------------------------------------------------------------------------
// helpers
// ---------------------------------------------------------------------------
__device__ __forceinline__ uint32_t smem_u32(const void* p) {
  return (uint32_t)__cvta_generic_to_shared(p);
}
__device__ __forceinline__ void ldmx4(uint32_t& r0, uint32_t& r1, uint32_t& r2,
                                      uint32_t& r3, uint32_t addr) {
  asm volatile("ldmatrix.sync.aligned.m8n8.x4.shared.b16 {%0,%1,%2,%3},[%4];"
               : "=r"(r0), "=r"(r1), "=r"(r2), "=r"(r3) : "r"(addr));
}
__device__ __forceinline__ void ldmx4t(uint32_t& r0, uint32_t& r1, uint32_t& r2,
                                       uint32_t& r3, uint32_t addr) {
  asm volatile("ldmatrix.sync.aligned.m8n8.x4.trans.shared.b16 {%0,%1,%2,%3},[%4];"
               : "=r"(r0), "=r"(r1), "=r"(r2), "=r"(r3) : "r"(addr));
}
__device__ __forceinline__ void mma16816(float* c, uint32_t a0, uint32_t a1,
                                         uint32_t a2, uint32_t a3, uint32_t b0,
                                         uint32_t b1) {
  asm volatile(
      "mma.sync.aligned.m16n8k16.row.col.f32.bf16.bf16.f32 "
      "{%0,%1,%2,%3},{%4,%5,%6,%7},{%8,%9},{%0,%1,%2,%3};"
      : "+f"(c[0]), "+f"(c[1]), "+f"(c[2]), "+f"(c[3])
      : "r"(a0), "r"(a1), "r"(a2), "r"(a3), "r"(b0), "r"(b1));
}
__device__ __forceinline__ uint32_t packbf(float lo, float hi) {
  uint32_t r;
  asm("cvt.rn.bf16x2.f32 %0, %1, %2;" : "=r"(r) : "f"(hi), "f"(lo));
  return r;
}

// ---------------------------------------------------------------------------
// fp32 -> bf16 cast
// ---------------------------------------------------------------------------
__global__ void cast_kernel(const float* __restrict__ src, bf16* __restrict__ dst,
                            int n4) {
  int i = blockIdx.x * blockDim.x + threadIdx.x;
  if (i < n4) {
    float4 v = ((const float4*)src)[i];
    ((__nv_bfloat162*)dst)[2 * i]     = __floats2bfloat162_rn(v.x, v.y);
    ((__nv_bfloat162*)dst)[2 * i + 1] = __floats2bfloat162_rn(v.z, v.w);
  }
}

// ---------------------------------------------------------------------------
// Merged QKV projection (bf16 HMMA), warp tile M32xN64.
// grid.x: 0 -> Q, 1 -> K, 2..9 -> V chunk (x-2). 128x128 CTA tile, 8 warps:
// wy = warp>>1 (32-row group), wx = warp&1 (64-col group).
// ---------------------------------------------------------------------------
__global__ __launch_bounds__(256) void proj_mma(void) {
  __shared__ bf16 Xs[128 * 72];
  __shared__ bf16 Ws[128 * 72];

  const int sel = blockIdx.x;
  const int bh = blockIdx.z, b = bh >> 3, h = bh & 7;
  const int n0 = blockIdx.y * 128;
  const int E  = (sel < 2) ? DK_ : DV_;
  const int e0 = (sel < 2) ? 0 : (sel - 2) * 128;
  const bf16* Wbase = (sel == 0) ? g_Wqb : (sel == 1) ? g_Wkb : g_Wvb;
  bf16* obase       = (sel == 0) ? g_Q   : (sel == 1) ? g_K   : g_V;

  const bf16* Xg = g_Xb + ((size_t)(b * N_ + n0)) * D_;
  const bf16* Wg = Wbase + ((size_t)h * E + e0) * (size_t)D_;

  const int tid = threadIdx.x, warp = tid >> 5, lane = tid & 31;
  const int gid = lane >> 2, tig = lane & 3;
  const int wy = warp >> 1, wx = warp & 1;
  const int m = lane >> 3;
  const uint32_t xs = smem_u32(Xs), ws = smem_u32(Ws);

  float acc[2][8][4] = {};

  for (int k0 = 0; k0 < D_; k0 += 64) {
#pragma unroll
    for (int r = 0; r < 4; ++r) {
      int f = tid + 256 * r;
      int row = f >> 3, c8 = (f & 7) * 8;
      *(uint4*)&Xs[row * 72 + c8] = *(const uint4*)(Xg + (size_t)row * D_ + k0 + c8);
      *(uint4*)&Ws[row * 72 + c8] = *(const uint4*)(Wg + (size_t)row * D_ + k0 + c8);
    }
    __syncthreads();

#pragma unroll
    for (int kk = 0; kk < 64; kk += 16) {
      uint32_t A[2][4];
#pragma unroll
      for (int mi = 0; mi < 2; ++mi) {
        int row = wy * 32 + mi * 16 + (lane & 7) + (m & 1) * 8;
        int col = kk + (m >> 1) * 8;
        ldmx4(A[mi][0], A[mi][1], A[mi][2], A[mi][3],
              xs + (uint32_t)(row * 72 + col) * 2);
      }
#pragma unroll
      for (int j = 0; j < 4; ++j) {
        uint32_t b0, b1, b2, b3;
        int row = wx * 64 + j * 16 + (lane & 7) + (m >> 1) * 8;
        int col = kk + (m & 1) * 8;
        ldmx4(b0, b1, b2, b3, ws + (uint32_t)(row * 72 + col) * 2);
#pragma unroll
        for (int mi = 0; mi < 2; ++mi) {
          mma16816(acc[mi][2 * j],     A[mi][0], A[mi][1], A[mi][2], A[mi][3], b0, b1);
          mma16816(acc[mi][2 * j + 1], A[mi][0], A[mi][1], A[mi][2], A[mi][3], b2, b3);
        }
      }
    }
    __syncthreads();
  }

  bf16* og = obase + ((size_t)bh * N_ + n0) * E + e0;
#pragma unroll
  for (int mi = 0; mi < 2; ++mi) {
    int rb = wy * 32 + mi * 16;
#pragma unroll
    for (int nj = 0; nj < 8; ++nj) {
      int col = wx * 64 + nj * 8 + tig * 2;
      *(uint32_t*)(og + (size_t)(rb + gid) * E + col) =
          packbf(acc[mi][nj][0], acc[mi][nj][1]);
      *(uint32_t*)(og + (size_t)(rb + gid + 8) * E + col) =
          packbf(acc[mi][nj][2], acc[mi][nj][3]);
    }
  }
}

// ---------------------------------------------------------------------------
// Score kernel: S[bh][n][m] = (m<=n) ? relu(Q.K^T)/N : 0, bf16.
// 128x128 tile, 8 warps, warp tile M32xN64. Upper-tri blocks exit.
// ---------------------------------------------------------------------------
__global__ __launch_bounds__(256) void score_mma(void) {
  const int ki = blockIdx.x, qi = blockIdx.y;
  if (ki > qi) return;
  const int bh = blockIdx.z;

  extern __shared__ bf16 ssm[];
  bf16* Qs = ssm;               // [128][136]
  bf16* Ks = Qs + 128 * 136;    // [128][136]

  const int q0 = qi * 128, k0 = ki * 128;
  const int tid = threadIdx.x, warp = tid >> 5, lane = tid & 31;
  const int gid = lane >> 2, tig = lane & 3;
  const int wy = warp >> 1, wx = warp & 1;
  const int m = lane >> 3;
  const uint32_t qs = smem_u32(Qs), ks = smem_u32(Ks);
  const float invN = 1.0f / (float)N_;

  const bf16* Qg = g_Q + ((size_t)bh * N_ + q0) * DK_;
  const bf16* Kg = g_K + ((size_t)bh * N_ + k0) * DK_;

#pragma unroll
  for (int r = 0; r < 8; ++r) {
    int f = tid + 256 * r;
    int row = f >> 4, c8 = (f & 15) * 8;
    *(uint4*)&Qs[row * 136 + c8] = *(const uint4*)(Qg + (size_t)row * DK_ + c8);
    *(uint4*)&Ks[row * 136 + c8] = *(const uint4*)(Kg + (size_t)row * DK_ + c8);
  }
  __syncthreads();

  float acc[2][8][4] = {};
#pragma unroll
  for (int kk = 0; kk < DK_; kk += 16) {
    uint32_t A[2][4];
#pragma unroll
    for (int mi = 0; mi < 2; ++mi) {
      int row = wy * 32 + mi * 16 + (lane & 7) + (m & 1) * 8;
      int col = kk + (m >> 1) * 8;
      ldmx4(A[mi][0], A[mi][1], A[mi][2], A[mi][3],
            qs + (uint32_t)(row * 136 + col) * 2);
    }
#pragma unroll
    for (int j = 0; j < 4; ++j) {
      uint32_t b0, b1, b2, b3;
      int row = wx * 64 + j * 16 + (lane & 7) + (m >> 1) * 8;
      int col = kk + (m & 1) * 8;
      ldmx4(b0, b1, b2, b3, ks + (uint32_t)(row * 136 + col) * 2);
#pragma unroll
      for (int mi = 0; mi < 2; ++mi) {
        mma16816(acc[mi][2 * j],     A[mi][0], A[mi][1], A[mi][2], A[mi][3], b0, b1);
        mma16816(acc[mi][2 * j + 1], A[mi][0], A[mi][1], A[mi][2], A[mi][3], b2, b3);
      }
    }
  }

  bf16* Sg = g_S + (size_t)bh * N_ * N_;
#pragma unroll
  for (int mi = 0; mi < 2; ++mi) {
    int r0 = q0 + wy * 32 + mi * 16 + gid;
    int r1 = r0 + 8;
#pragma unroll
    for (int nj = 0; nj < 8; ++nj) {
      int c = k0 + wx * 64 + nj * 8 + tig * 2;
      float v0f = (c     <= r0) ? fmaxf(acc[mi][nj][0], 0.f) * invN : 0.f;
      float v1f = (c + 1 <= r0) ? fmaxf(acc[mi][nj][1], 0.f) * invN : 0.f;
      float v2f = (c     <= r1) ? fmaxf(acc[mi][nj][2], 0.f) * invN : 0.f;
      float v3f = (c + 1 <= r1) ? fmaxf(acc[mi][nj][3], 0.f) * invN : 0.f;
      *(uint32_t*)(Sg + (size_t)r0 * N_ + c) = packbf(v0f, v1f);
      *(uint32_t*)(Sg + (size_t)r1 * N_ + c) = packbf(v2f, v3f);
    }
  }
}

// ---------------------------------------------------------------------------
// PV GEMM + residual: out[b][n][v] = x + sum_h sum_m S[bh][n][m] * V[bh][m][v]
// Block: (v-chunk 128, q-tile 128, b). 8 warps, warp tile M32xN64.
// ---------------------------------------------------------------------------
__global__ __launch_bounds__(256) void pv_mma(const float* __restrict__ X,
                                              float* __restrict__ out) {
  extern __shared__ bf16 psm[];
  bf16* Ss = psm;               // [128][72]
  bf16* Vs = Ss + 128 * 72;     // [64][136]

  const int b  = blockIdx.z;
  const int qi = blockIdx.y;
  const int q0 = qi * 128;
  const int v0 = blockIdx.x * 128;
  const int tid = threadIdx.x, warp = tid >> 5, lane = tid & 31;
  const int gid = lane >> 2, tig = lane & 3;
  const int wy = warp >> 1, wx = warp & 1;
  const int m = lane >> 3;
  const uint32_t ss = smem_u32(Ss), vs = smem_u32(Vs);
  const int nkt = 2 * qi + 2;  // 64-wide key tiles, m < q0+128

  float acc[2][8][4] = {};

  for (int h = 0; h < H_; ++h) {
    const size_t bh = (size_t)(b * H_ + h);
    const bf16* Sg = g_S + (bh * N_ + q0) * (size_t)N_;
    const bf16* Vg = g_V + bh * (size_t)N_ * DV_ + v0;

    for (int kt = 0; kt < nkt; ++kt) {
      const int k0 = kt * 64;
      __syncthreads();
#pragma unroll
      for (int r = 0; r < 4; ++r) {
        int f = tid + 256 * r;
        int srow = f >> 3, sc8 = (f & 7) * 8;
        *(uint4*)&Ss[srow * 72 + sc8] =
            *(const uint4*)(Sg + (size_t)srow * N_ + k0 + sc8);
        int vrow = f >> 4, vc8 = (f & 15) * 8;
        *(uint4*)&Vs[vrow * 136 + vc8] =
            *(const uint4*)(Vg + (size_t)(k0 + vrow) * DV_ + vc8);
      }
      __syncthreads();

#pragma unroll
      for (int kk = 0; kk < 64; kk += 16) {
        uint32_t A[2][4];
#pragma unroll
        for (int mi = 0; mi < 2; ++mi) {
          int row = wy * 32 + mi * 16 + (lane & 7) + (m & 1) * 8;
          int col = kk + (m >> 1) * 8;
          ldmx4(A[mi][0], A[mi][1], A[mi][2], A[mi][3],
                ss + (uint32_t)(row * 72 + col) * 2);
        }
#pragma unroll
        for (int j = 0; j < 4; ++j) {
          uint32_t b0, b1, b2, b3;
          int row = kk + (m & 1) * 8 + (lane & 7);
          int col = wx * 64 + j * 16 + (m >> 1) * 8;
          ldmx4t(b0, b1, b2, b3, vs + (uint32_t)(row * 136 + col) * 2);
#pragma unroll
          for (int mi = 0; mi < 2; ++mi) {
            mma16816(acc[mi][2 * j],     A[mi][0], A[mi][1], A[mi][2], A[mi][3], b0, b1);
            mma16816(acc[mi][2 * j + 1], A[mi][0], A[mi][1], A[mi][2], A[mi][3], b2, b3);
          }
        }
      }
    }
  }

  // epilogue: out = x + O
#pragma unroll
  for (int mi = 0; mi < 2; ++mi) {
    int rb = q0 + wy * 32 + mi * 16;
#pragma unroll
    for (int nj = 0; nj < 8; ++nj) {
      int col = v0 + wx * 64 + nj * 8 + tig * 2;
      size_t i0 = ((size_t)b * N_ + rb + gid) * DV_ + col;
      size_t i1 = ((size_t)b * N_ + rb + gid + 8) * DV_ + col;
      float2 a = *(const float2*)(X + i0);
      float2 c = *(const float2*)(X + i1);
      *(float2*)(out + i0) = make_float2(a.x + acc[mi][nj][0], a.y + acc[mi][nj][1]);
      *(float2*)(out + i1) = make_float2(c.x + acc[mi][nj][2], c.y + acc[mi][nj][3]);
    }
  }
}

// ---------------------------------------------------------------------------
extern "C" void kernel_launch(void* const* d_in, const int* in_sizes, int n_in,
                              void* d_out, int out_size) {
  const float* x  = (const float*)d_in[0];
  const float* Wq = (const float*)d_in[1];
  const float* Wk = (const float*)d_in[2];
  const float* Wv = (const float*)d_in[3];
  float* out = (float*)d_out;

  bf16 *Xb, *Wqb, *Wkb, *Wvb;
  cudaGetSymbolAddress((void**)&Xb,  g_Xb);
  cudaGetSymbolAddress((void**)&Wqb, g_Wqb);
  cudaGetSymbolAddress((void**)&Wkb, g_Wkb);
  cudaGetSymbolAddress((void**)&Wvb, g_Wvb);

  auto cast = [&](const float* s, bf16* d, int n) {
    int n4 = n / 4;
    cast_kernel<<<(n4 + 255) / 256, 256>>>(s, d, n4);
  };
  cast(x,  Xb,  B_ * N_ * D_);
  cast(Wq, Wqb, H_ * DK_ * D_);
  cast(Wk, Wkb, H_ * DK_ * D_);
  cast(Wv, Wvb, H_ * DV_ * D_);

  proj_mma<<<dim3(10, 16, 16), 256>>>();

  const int score_smem = 2 * 128 * 136 * (int)sizeof(bf16);  // 69632
  cudaFuncSetAttribute(score_mma, cudaFuncAttributeMaxDynamicSharedMemorySize,
                       score_smem);
  score_mma<<<dim3(16, 16, 16), 256, score_smem>>>();

  const int pv_smem = (128 * 72 + 64 * 136) * (int)sizeof(bf16);  // 35840
  cudaFuncSetAttribute(pv_mma, cudaFuncAttributeMaxDynamicSharedMemorySize,
                       pv_smem);
  pv_mma<<<dim3(8, 16, 2), 256, pv_smem>>>(x, out);
}